// round 1
// baseline (speedup 1.0000x reference)
#include <cuda_runtime.h>
#include <cuda_bf16.h>
#include <cstdint>

// Problem dims
#define G1 512
#define E_EDGES 16384
#define S1 8192
#define S2 8192
#define BATCH 256
#define BT 128          // batch tile per CTA

// -------- device scratch (no allocations allowed) --------
__device__ int g_counts[G1];
__device__ int g_cursor[G1];
__device__ int g_offsets[G1 + 1];
__device__ int g_edge_list[E_EDGES];   // packed: (t1 << 16) | e

// -------- precompute kernels: CSR bucketing by t0 --------
__global__ void init_kernel() {
    int t = threadIdx.x;
    if (t < G1) { g_counts[t] = 0; g_cursor[t] = 0; }
}

__global__ void hist_kernel(const int* __restrict__ edge_index) {
    int e = blockIdx.x * blockDim.x + threadIdx.x;
    if (e < E_EDGES) {
        int t0 = edge_index[e];
        atomicAdd(&g_counts[t0], 1);
    }
}

__global__ void scan_kernel() {
    __shared__ int s[G1];
    int t = threadIdx.x;
    s[t] = g_counts[t];
    __syncthreads();
    #pragma unroll
    for (int d = 1; d < G1; d <<= 1) {
        int v = (t >= d) ? s[t - d] : 0;
        __syncthreads();
        s[t] += v;
        __syncthreads();
    }
    g_offsets[t + 1] = s[t];   // inclusive -> exclusive via shift
    if (t == 0) g_offsets[0] = 0;
}

__global__ void scatter_kernel(const int* __restrict__ edge_index) {
    int e = blockIdx.x * blockDim.x + threadIdx.x;
    if (e < E_EDGES) {
        int t0 = edge_index[e];
        int t1 = edge_index[E_EDGES + e];
        int pos = atomicAdd(&g_cursor[t0], 1);
        g_edge_list[g_offsets[t0] + pos] = (t1 << 16) | e;
    }
}

// -------- main SpMM kernel --------
// grid: (512 t0-blocks, 2 batch tiles), 256 threads
// thread (j = tid&15, bq = tid>>4) computes out[bbase + bq*8 + bb, t0*16 + j], bb=0..7
__global__ __launch_bounds__(256) void spmm_kernel(
    const float* __restrict__ x,
    const float* __restrict__ values,
    const float* __restrict__ bias,
    float* __restrict__ out)
{
    __shared__ float vraw[256];          // V block, layout i*16 + j
    __shared__ float4 xs4[BT][5];        // x tile: [b_local][i4], padded row (80B) vs conflicts

    const int t0    = blockIdx.x;
    const int bbase = blockIdx.y * BT;
    const int tid   = threadIdx.x;
    const int j     = tid & 15;
    const int bq    = tid >> 4;          // 0..15

    const float bv = bias[t0 * 16 + j];

    float acc[8];
    #pragma unroll
    for (int bb = 0; bb < 8; bb++) acc[bb] = 0.0f;

    const int beg = g_offsets[t0];
    const int end = g_offsets[t0 + 1];

    for (int k = beg; k < end; k++) {
        const int packed = g_edge_list[k];
        const int e  = packed & 0xFFFF;
        const int t1 = packed >> 16;

        __syncthreads();   // previous iteration's compute done before smem overwrite

        // stage V block (256 floats, fully coalesced)
        vraw[tid] = values[(e << 8) + tid];

        // stage x tile: 128 rows x 16 floats = 512 float4, 2 per thread
        {
            const float4* xg = reinterpret_cast<const float4*>(
                x + (size_t)bbase * S1 + t1 * 16);
            int lin = tid;
            int bl = lin >> 2, i4 = lin & 3;
            xs4[bl][i4] = xg[(size_t)bl * (S1 / 4) + i4];
            lin = tid + 256;
            bl = lin >> 2; i4 = lin & 3;
            xs4[bl][i4] = xg[(size_t)bl * (S1 / 4) + i4];
        }
        __syncthreads();

        // compute: register-blocked, float4 x reads
        #pragma unroll
        for (int i4 = 0; i4 < 4; i4++) {
            float4 vv;
            vv.x = vraw[(i4 * 4 + 0) * 16 + j];
            vv.y = vraw[(i4 * 4 + 1) * 16 + j];
            vv.z = vraw[(i4 * 4 + 2) * 16 + j];
            vv.w = vraw[(i4 * 4 + 3) * 16 + j];
            #pragma unroll
            for (int bb = 0; bb < 8; bb++) {
                float4 xv = xs4[bq * 8 + bb][i4];
                acc[bb] += xv.x * vv.x;
                acc[bb] += xv.y * vv.y;
                acc[bb] += xv.z * vv.z;
                acc[bb] += xv.w * vv.w;
            }
        }
    }

    #pragma unroll
    for (int bb = 0; bb < 8; bb++) {
        out[(size_t)(bbase + bq * 8 + bb) * S2 + t0 * 16 + j] = acc[bb] + bv;
    }
}

// -------- launch --------
extern "C" void kernel_launch(void* const* d_in, const int* in_sizes, int n_in,
                              void* d_out, int out_size) {
    const float* x      = (const float*)d_in[0];   // (256, 8192)
    const float* values = (const float*)d_in[1];   // (4194304,)
    const float* bias   = (const float*)d_in[2];   // (8192,)
    const int*   eidx   = (const int*)d_in[3];     // (2, 16384)
    float* out = (float*)d_out;                    // (256, 8192)

    init_kernel<<<1, G1>>>();
    hist_kernel<<<E_EDGES / 256, 256>>>(eidx);
    scan_kernel<<<1, G1>>>();
    scatter_kernel<<<E_EDGES / 256, 256>>>(eidx);

    dim3 grid(G1, BATCH / BT);
    spmm_kernel<<<grid, 256>>>(x, values, bias, out);
}

// round 2
// speedup vs baseline: 1.3033x; 1.3033x over previous
#include <cuda_runtime.h>
#include <cuda_bf16.h>
#include <cstdint>

// Problem dims
#define G1 512
#define E_EDGES 16384
#define S1 8192
#define S2 8192
#define BATCH 256
#define BT 128          // batch tile per CTA

typedef unsigned long long ull;

// -------- device scratch (no allocations allowed) --------
__device__ int g_counts[G1];
__device__ int g_cursor[G1];
__device__ int g_offsets[G1 + 1];
__device__ int g_edge_list[E_EDGES];   // packed: (t1 << 16) | e

// -------- precompute kernels: CSR bucketing by t0 --------
__global__ void init_kernel() {
    int t = threadIdx.x;
    if (t < G1) { g_counts[t] = 0; g_cursor[t] = 0; }
}

__global__ void hist_kernel(const int* __restrict__ edge_index) {
    int e = blockIdx.x * blockDim.x + threadIdx.x;
    if (e < E_EDGES) {
        int t0 = edge_index[e];
        atomicAdd(&g_counts[t0], 1);
    }
}

__global__ void scan_kernel() {
    __shared__ int s[G1];
    int t = threadIdx.x;
    s[t] = g_counts[t];
    __syncthreads();
    #pragma unroll
    for (int d = 1; d < G1; d <<= 1) {
        int v = (t >= d) ? s[t - d] : 0;
        __syncthreads();
        s[t] += v;
        __syncthreads();
    }
    g_offsets[t + 1] = s[t];
    if (t == 0) g_offsets[0] = 0;
}

__global__ void scatter_kernel(const int* __restrict__ edge_index) {
    int e = blockIdx.x * blockDim.x + threadIdx.x;
    if (e < E_EDGES) {
        int t0 = edge_index[e];
        int t1 = edge_index[E_EDGES + e];
        int pos = atomicAdd(&g_cursor[t0], 1);
        g_edge_list[g_offsets[t0] + pos] = (t1 << 16) | e;
    }
}

// packed fp32x2 FMA (Blackwell): d = a*b + d, lanewise on 2 floats in a b64 reg
__device__ __forceinline__ void fma2(ull& d, ull a, ull b) {
    asm("fma.rn.f32x2 %0, %1, %2, %0;" : "+l"(d) : "l"(a), "l"(b));
}

union F2U { ull u; float2 f; };

// -------- main SpMM kernel --------
// grid: (512 t0-blocks, 2 batch tiles), 128 threads
// thread (jp = tid&7, bq = tid>>3): outputs j = {2jp, 2jp+1}, b = bq*8 .. bq*8+7
__global__ __launch_bounds__(128) void spmm_kernel(
    const float* __restrict__ x,
    const float* __restrict__ values,
    const float* __restrict__ bias,
    float* __restrict__ out)
{
    // double-buffered transposed x tile: xs[buf][i][b_rot], stride 132 (16B aligned rows)
    __shared__ float xs[2][16][132];
    // double-buffered duplicated V: vd[buf][i*16+j] = (v,v)
    __shared__ ull vd[2][256];

    const int tid   = threadIdx.x;
    const int jp    = tid & 7;       // j pair index
    const int bq    = tid >> 3;      // 0..15, batch octet
    const int t0    = blockIdx.x;
    const int bbase = blockIdx.y * BT;

    ull acc0[4] = {0ull, 0ull, 0ull, 0ull};   // j = 2jp
    ull acc1[4] = {0ull, 0ull, 0ull, 0ull};   // j = 2jp+1

    const int beg = g_offsets[t0];
    const int end = g_offsets[t0 + 1];

    // staging assignment: lin = tid + 128k -> (bl = lin>>2, i4 = lin&3)
    int c = 0;
    if (beg < end) {
        float4 R[4];
        float vA, vB;
        int packed = g_edge_list[beg];

        // ---- prologue LDG for first edge ----
        {
            const int e  = packed & 0xFFFF;
            const int t1 = packed >> 16;
            const float4* xg = reinterpret_cast<const float4*>(
                x + (size_t)bbase * S1 + t1 * 16);
            #pragma unroll
            for (int k = 0; k < 4; k++) {
                int lin = tid + (k << 7);
                R[k] = __ldg(&xg[(size_t)(lin >> 2) * (S1 / 4) + (lin & 3)]);
            }
            const float* vp = values + ((size_t)e << 8);
            vA = __ldg(vp + tid);
            vB = __ldg(vp + tid + 128);
        }

        for (int k = beg; k < end; k++) {
            // ---- STS current edge into buf c (conflict-free: col rotated by 8*i4) ----
            #pragma unroll
            for (int q = 0; q < 4; q++) {
                int lin = tid + (q << 7);
                int bl  = lin >> 2;
                int i4  = lin & 3;
                int col = (bl + (i4 << 3)) & 127;
                xs[c][i4 * 4 + 0][col] = R[q].x;
                xs[c][i4 * 4 + 1][col] = R[q].y;
                xs[c][i4 * 4 + 2][col] = R[q].z;
                xs[c][i4 * 4 + 3][col] = R[q].w;
            }
            {
                unsigned ua = __float_as_uint(vA);
                unsigned ub = __float_as_uint(vB);
                vd[c][tid]       = (ull)ua | ((ull)ua << 32);
                vd[c][tid + 128] = (ull)ub | ((ull)ub << 32);
            }

            int pnext = 0;
            if (k + 1 < end) pnext = g_edge_list[k + 1];

            __syncthreads();   // buf c fully staged

            // ---- LDG next edge (overlaps with compute below) ----
            if (k + 1 < end) {
                const int e  = pnext & 0xFFFF;
                const int t1 = pnext >> 16;
                const float4* xg = reinterpret_cast<const float4*>(
                    x + (size_t)bbase * S1 + t1 * 16);
                #pragma unroll
                for (int q = 0; q < 4; q++) {
                    int lin = tid + (q << 7);
                    R[q] = __ldg(&xg[(size_t)(lin >> 2) * (S1 / 4) + (lin & 3)]);
                }
                const float* vp = values + ((size_t)e << 8);
                vA = __ldg(vp + tid);
                vB = __ldg(vp + tid + 128);
            }

            // ---- compute on buf c ----
            #pragma unroll
            for (int i = 0; i < 16; i++) {
                const int i4 = i >> 2;
                const int m  = ((bq + i4) << 3) & 127;  // rotated column base
                ull va = vd[c][i * 16 + 2 * jp];
                ull vb = vd[c][i * 16 + 2 * jp + 1];
                const float* xr = &xs[c][i][m];
                #pragma unroll
                for (int p = 0; p < 4; p++) {
                    ull xp = *reinterpret_cast<const ull*>(xr + 2 * p);
                    fma2(acc0[p], xp, va);
                    fma2(acc1[p], xp, vb);
                }
            }
            c ^= 1;
        }
    }

    // ---- epilogue: add bias, write float2 per (b, j-pair) ----
    const float bv0 = bias[t0 * 16 + 2 * jp];
    const float bv1 = bias[t0 * 16 + 2 * jp + 1];
    #pragma unroll
    for (int p = 0; p < 4; p++) {
        F2U a0, a1;
        a0.u = acc0[p];
        a1.u = acc1[p];
        const int b0 = bbase + bq * 8 + 2 * p;
        float2 o0 = make_float2(a0.f.x + bv0, a1.f.x + bv1);
        float2 o1 = make_float2(a0.f.y + bv0, a1.f.y + bv1);
        *reinterpret_cast<float2*>(out + (size_t)b0 * S2 + t0 * 16 + 2 * jp)       = o0;
        *reinterpret_cast<float2*>(out + (size_t)(b0 + 1) * S2 + t0 * 16 + 2 * jp) = o1;
    }
}

// -------- launch --------
extern "C" void kernel_launch(void* const* d_in, const int* in_sizes, int n_in,
                              void* d_out, int out_size) {
    const float* x      = (const float*)d_in[0];   // (256, 8192)
    const float* values = (const float*)d_in[1];   // (4194304,)
    const float* bias   = (const float*)d_in[2];   // (8192,)
    const int*   eidx   = (const int*)d_in[3];     // (2, 16384)
    float* out = (float*)d_out;                    // (256, 8192)

    init_kernel<<<1, G1>>>();
    hist_kernel<<<E_EDGES / 128, 128>>>(eidx);
    scan_kernel<<<1, G1>>>();
    scatter_kernel<<<E_EDGES / 128, 128>>>(eidx);

    dim3 grid(G1, BATCH / BT);
    spmm_kernel<<<grid, 128>>>(x, values, bias, out);
}